// round 9
// baseline (speedup 1.0000x reference)
#include <cuda_runtime.h>
#include <cuda_fp16.h>
#include <math.h>
#include <stdint.h>

#define DIM 512
#define NN 50000
#define NE 100000
#define TOTE (2*NE)
#define NRELS 4
#define FFDIM 1024
#define NNP 50176              // 98*512, padded per-rel stride for scan alignment
#define SCAN_NB 392            // 4*98 blocks of 512

// ---------------- scratch (device globals; no allocation allowed) -------------
__device__ __half g_yh[NRELS*NN*DIM];    // per-rel transformed nodes (fp16, compact rows)
__device__ float g_deg[NN];
__device__ float g_base[NN*DIM];
__device__ __half g_baseh[NN*DIM];
__device__ float g_agg[NN*DIM];          // scatter target / reused as FFN2 out
__device__ float g_self[NN*DIM];
__device__ float g_x1[NN*DIM];
__device__ __half g_x1h[NN*DIM];
__device__ __half g_uh[NN*FFDIM];        // FFN hidden (post-gelu) fp16
#define NWELEM 2359296
#define WREL_OFF 0
#define WSELF_OFF 1048576
#define WF1_OFF 1310720
#define WF2_OFF 1835008
__device__ __half g_wh[NWELEM];
__device__ float g_part[256*DIM];
__device__ int   g_is64;
// compaction state
__device__ int g_mark[NRELS*NNP];        // 200704 = 392*512
__device__ int g_bsum[SCAN_NB];
__device__ int g_boff[SCAN_NB+8];
__device__ int g_cnt[NRELS];
__device__ int g_rowlist[NRELS*NN];      // compact idx -> src node (per rel)
__device__ int g_posmap[NRELS*NNP];      // (rel,src) -> compact idx

// ---------------- index dtype detection --------------------------------------
__global__ void detect_idx_kernel(const unsigned int* __restrict__ w) {
    __shared__ int nz;
    if (threadIdx.x == 0) nz = 0;
    __syncthreads();
    int found = 0;
    for (int i = threadIdx.x; i < TOTE/2 * 2; i += blockDim.x) {
        if (w[2*i + 1] != 0u) { found = 1; break; }
        if (2*i + 1 >= TOTE - 1) break;
    }
    if (found) atomicOr(&nz, 1);
    __syncthreads();
    if (threadIdx.x == 0) g_is64 = nz ? 0 : 1;
}

__device__ __forceinline__ int ldidx(const void* p, long long i) {
    return g_is64 ? (int)((const long long*)p)[i] : ((const int*)p)[i];
}

// ---------------- edge decode --------------------------------------------------
__device__ __forceinline__ void edge_decode(const void* ei, const void* et,
                                            const float* ew, int e,
                                            int& src, int& dst, int& rel, float& w) {
    if (e < NE) {
        src = ldidx(ei, e); dst = ldidx(ei, NE + e);
        rel = ldidx(et, e); w = ew[e];
    } else {
        int e2 = e - NE;
        src = ldidx(ei, NE + e2); dst = ldidx(ei, e2);
        rel = ldidx(et, e2) + 2;  w = ew[e2];
    }
}

// ---------------- zero agg + deg + mark ---------------------------------------
__global__ void zero_kernel() {
    long long n4 = (long long)NN*DIM/4;
    float4* s4 = (float4*)g_agg;
    float4 z = make_float4(0.f,0.f,0.f,0.f);
    long long stride = (long long)gridDim.x * blockDim.x;
    for (long long i = (long long)blockIdx.x*blockDim.x + threadIdx.x; i < n4; i += stride)
        s4[i] = z;
    for (int i = blockIdx.x*blockDim.x + threadIdx.x; i < NN; i += (int)stride)
        g_deg[i] = 0.f;
    for (int i = blockIdx.x*blockDim.x + threadIdx.x; i < NRELS*NNP; i += (int)stride)
        g_mark[i] = 0;
}

// ---------------- compaction: mark / scan / write ------------------------------
__global__ void mark_kernel(const void* __restrict__ ei, const void* __restrict__ et,
                            const float* __restrict__ ew) {
    int e = blockIdx.x * blockDim.x + threadIdx.x;
    if (e >= TOTE) return;
    int src, dst, rel; float w;
    edge_decode(ei, et, ew, e, src, dst, rel, w);
    g_mark[rel*NNP + src] = 1;
}

__global__ void scan_sum_kernel() {          // SCAN_NB blocks x 512
    __shared__ int sh[512];
    int b = blockIdx.x, t = threadIdx.x;
    sh[t] = g_mark[b*512 + t];
    __syncthreads();
    for (int s = 256; s > 0; s >>= 1) {
        if (t < s) sh[t] += sh[t+s];
        __syncthreads();
    }
    if (t == 0) g_bsum[b] = sh[0];
}

__global__ void scan_off_kernel() {          // 1 block x 512
    __shared__ int sh[512];
    int t = threadIdx.x;
    sh[t] = (t < SCAN_NB) ? g_bsum[t] : 0;
    __syncthreads();
    for (int s = 1; s < 512; s <<= 1) {
        int v = (t >= s) ? sh[t-s] : 0;
        __syncthreads();
        sh[t] += v;
        __syncthreads();
    }
    if (t < SCAN_NB) g_boff[t+1] = sh[t];
    if (t == 0) g_boff[0] = 0;
    __syncthreads();
    if (t < NRELS) {
        int lo = (t == 0) ? 0 : sh[98*t - 1];
        int hi = sh[98*(t+1) - 1];
        g_cnt[t] = hi - lo;
    }
}

__global__ void scan_write_kernel() {        // SCAN_NB blocks x 512
    __shared__ int sh[512];
    int b = blockIdx.x, t = threadIdx.x;
    int j = b*512 + t;
    int m = g_mark[j];
    sh[t] = m;
    __syncthreads();
    for (int s = 1; s < 512; s <<= 1) {
        int v = (t >= s) ? sh[t-s] : 0;
        __syncthreads();
        sh[t] += v;
        __syncthreads();
    }
    if (m) {
        int gpos = g_boff[b] + sh[t] - m;   // exclusive global position
        int rel = b / 98;
        int src = j - rel*NNP;
        int li = gpos - g_boff[rel*98];
        g_rowlist[rel*NN + li] = src;
        g_posmap[j] = li;
    }
}

// ---------------- input LayerNorm ---------------------------------------------
__global__ void input_ln_kernel(const float* __restrict__ nf, const void* __restrict__ ntype,
                                const float* __restrict__ emb, const float* __restrict__ gw,
                                const float* __restrict__ gb) {
    __shared__ float2 red[256];
    int row = blockIdx.x, t = threadIdx.x;
    int nt = ldidx(ntype, row);
    long long off = (long long)row * DIM;
    float v0 = nf[off + t]       + emb[nt*DIM + t];
    float v1 = nf[off + t + 256] + emb[nt*DIM + t + 256];
    red[t] = make_float2(v0 + v1, v0*v0 + v1*v1);
    __syncthreads();
    for (int s = 128; s > 0; s >>= 1) {
        if (t < s) { red[t].x += red[t+s].x; red[t].y += red[t+s].y; }
        __syncthreads();
    }
    float m = red[0].x * (1.f/DIM);
    float var = red[0].y * (1.f/DIM) - m*m;
    float r = rsqrtf(var + 1e-5f);
    float b0 = (v0 - m)*r*gw[t]     + gb[t];
    float b1 = (v1 - m)*r*gw[t+256] + gb[t+256];
    g_base[off + t]       = b0;
    g_base[off + t + 256] = b1;
    g_baseh[off + t]       = __float2half(b0);
    g_baseh[off + t + 256] = __float2half(b1);
}

// ---------------- edge scatter: agg[dst] += w * y[rel][pos(src)] ---------------
__global__ void scatter_kernel(const void* __restrict__ ei, const void* __restrict__ et,
                               const float* __restrict__ ew) {
    int e = blockIdx.x;
    int t = threadIdx.x;   // 0..127, 4 halves each
    int src, dst, rel; float w;
    edge_decode(ei, et, ew, e, src, dst, rel, w);
    int li = g_posmap[rel*NNP + src];
    const uint2* yrow = (const uint2*)(g_yh + ((long long)rel*NN + li)*DIM);
    uint2 pk = yrow[t];
    __half2 p0 = *(__half2*)&pk.x;
    __half2 p1 = *(__half2*)&pk.y;
    float4 v;
    v.x = w * __half2float(p0.x);
    v.y = w * __half2float(p0.y);
    v.z = w * __half2float(p1.x);
    v.w = w * __half2float(p1.y);
    float* p = g_agg + (long long)dst*DIM + t*4;
    asm volatile("red.global.add.v4.f32 [%0], {%1,%2,%3,%4};"
                 :: "l"(p), "f"(v.x), "f"(v.y), "f"(v.z), "f"(v.w) : "memory");
    if (t == 0) atomicAdd(&g_deg[dst], w);
}

// ---------------- weight convert ----------------------------------------------
__global__ void conv_w_kernel(const float* __restrict__ src, int n, int off) {
    for (int i = blockIdx.x*blockDim.x + threadIdx.x; i < n; i += gridDim.x*blockDim.x)
        g_wh[off + i] = __float2half(src[i]);
}

// ================= fp16 tensor-core GEMM (NT, mma.sync) =======================
#define GBM 128
#define GBN 128
#define GBK 32

__device__ __forceinline__ void ldsm4(uint32_t* r, uint32_t addr) {
    asm volatile("ldmatrix.sync.aligned.m8n8.x4.shared.b16 {%0,%1,%2,%3},[%4];\n"
        : "=r"(r[0]), "=r"(r[1]), "=r"(r[2]), "=r"(r[3]) : "r"(addr));
}
__device__ __forceinline__ void mma_f16(float* d, const uint32_t* a, uint32_t b0, uint32_t b1) {
    asm volatile("mma.sync.aligned.m16n8k16.row.col.f32.f16.f16.f32 "
        "{%0,%1,%2,%3},{%4,%5,%6,%7},{%8,%9},{%0,%1,%2,%3};\n"
        : "+f"(d[0]), "+f"(d[1]), "+f"(d[2]), "+f"(d[3])
        : "r"(a[0]), "r"(a[1]), "r"(a[2]), "r"(a[3]), "r"(b0), "r"(b1));
}
__device__ __forceinline__ void cp16(uint32_t dst, const void* src, int sz) {
    asm volatile("cp.async.cg.shared.global [%0],[%1],16,%2;\n" :: "r"(dst), "l"(src), "r"(sz));
}

// mode: 0 = fp32 C = acc (+bias if bias)   1 = fp16 O = acc + bias
//       2 = fp16 O = gelu(acc + bias)
// rowlist != null: A rows gathered via rowlist[z*NN + r], M_eff = g_cnt[z]
__global__ void __launch_bounds__(128) gemm_f16(
    const __half* __restrict__ A, const __half* __restrict__ B,
    float* __restrict__ C, __half* __restrict__ O, const float* __restrict__ bias,
    const int* __restrict__ rowlist,
    int M, int N, int K, long long bStrideZ, long long outStrideZ, long long biasStrideZ, int mode)
{
    extern __shared__ __align__(1024) char smraw[];
    const int tid = threadIdx.x;
    const int lane = tid & 31, wid = tid >> 5;
    const int wm = wid >> 1, wn = wid & 1;
    const int bm = blockIdx.y * GBM, bn = blockIdx.x * GBN, z = blockIdx.z;
    int Meff = M;
    const int* rlz = nullptr;
    if (rowlist) {
        Meff = g_cnt[z];
        if (bm >= Meff) return;
        rlz = rowlist + (long long)z * NN;
    }
    const __half* Bz = B + (long long)z * bStrideZ;
    const int niter = K / GBK;
    uint32_t smbase = (uint32_t)__cvta_generic_to_shared(smraw);

    float acc[4][8][4];
    #pragma unroll
    for (int i = 0; i < 4; i++)
        #pragma unroll
        for (int j = 0; j < 8; j++)
            #pragma unroll
            for (int c = 0; c < 4; c++) acc[i][j][c] = 0.f;

    auto issue_copy = [&](int stage, int it) {
        int kb = it * GBK;
        #pragma unroll
        for (int i = 0; i < 8; i++) {
            int id  = i * 128 + tid;
            int q   = id >> 9;
            int rem = id & 511;
            int row = rem >> 2, c = rem & 3;
            uint32_t dst = smbase + stage*16384 + q*8192
                         + (uint32_t)(row*64 + ((c ^ ((row>>1)&3)) << 4));
            int sz = 16;
            const __half* src;
            if (q == 0) {
                int gr = bm + row;
                int node;
                if (gr >= Meff) { sz = 0; node = 0; }
                else node = rlz ? rlz[gr] : gr;
                src = A + (long long)node*K + kb + c*8;
            } else {
                src = Bz + (long long)(bn + row)*K + kb + c*8;
            }
            cp16(dst, src, sz);
        }
        asm volatile("cp.async.commit_group;\n" ::: "memory");
    };

    issue_copy(0, 0);

    for (int it = 0; it < niter; ++it) {
        if (it + 1 < niter) {
            issue_copy((it + 1) & 1, it + 1);
            asm volatile("cp.async.wait_group 1;\n" ::: "memory");
        } else {
            asm volatile("cp.async.wait_group 0;\n" ::: "memory");
        }
        __syncthreads();

        uint32_t sA = smbase + (it & 1)*16384;
        uint32_t sB = sA + 8192;
        int rsel = lane & 15;
        #pragma unroll
        for (int kk = 0; kk < 2; kk++) {
            int csel = kk*2 + (lane >> 4);
            uint32_t ah[4][4], bh[4][4];
            #pragma unroll
            for (int mi = 0; mi < 4; mi++) {
                int row = wm*64 + mi*16 + rsel;
                uint32_t off = (uint32_t)(row*64 + ((csel ^ ((row>>1)&3)) << 4));
                ldsm4(ah[mi], sA + off);
            }
            #pragma unroll
            for (int p = 0; p < 4; p++) {
                int row = wn*64 + p*16 + rsel;
                uint32_t off = (uint32_t)(row*64 + ((csel ^ ((row>>1)&3)) << 4));
                ldsm4(bh[p], sB + off);
            }
            #pragma unroll
            for (int mi = 0; mi < 4; mi++)
                #pragma unroll
                for (int nj = 0; nj < 8; nj++) {
                    int p = nj >> 1, h = nj & 1;
                    mma_f16(acc[mi][nj], ah[mi], bh[p][h], bh[p][2+h]);
                }
        }
        __syncthreads();
    }

    // ---- epilogue -----------------------------------------------------------
    #pragma unroll
    for (int mi = 0; mi < 4; mi++) {
        #pragma unroll
        for (int nj = 0; nj < 8; nj++) {
            int gc = bn + wn*64 + nj*8 + (lane & 3)*2;
            #pragma unroll
            for (int half = 0; half < 2; half++) {
                int gr = bm + wm*64 + mi*16 + (lane >> 2) + half*8;
                if (gr >= Meff) continue;
                float v0 = acc[mi][nj][half*2 + 0];
                float v1 = acc[mi][nj][half*2 + 1];
                if (mode == 0) {
                    if (bias) {
                        const float* bs = bias + (long long)z*biasStrideZ;
                        v0 += bs[gc]; v1 += bs[gc+1];
                    }
                    float* Cp = C + (long long)z*outStrideZ + (long long)gr*N + gc;
                    float2 w2 = make_float2(v0, v1);
                    *(float2*)Cp = w2;
                } else {
                    const float* bs = bias + (long long)z*biasStrideZ;
                    v0 += bs[gc]; v1 += bs[gc+1];
                    if (mode == 2) {
                        v0 = 0.5f * v0 * (1.f + erff(v0 * 0.70710678118654752f));
                        v1 = 0.5f * v1 * (1.f + erff(v1 * 0.70710678118654752f));
                    }
                    __half2 o;
                    o.x = __float2half(v0);
                    o.y = __float2half(v1);
                    *(__half2*)(O + (long long)z*outStrideZ + (long long)gr*N + gc) = o;
                }
            }
        }
    }
}

// ---------------- LN1: x1 = LN(base + agg/max(deg,1) + self + b_self) ---------
__global__ void ln1_kernel(const float* __restrict__ b_self, const float* __restrict__ gw,
                           const float* __restrict__ gb) {
    __shared__ float2 red[256];
    int row = blockIdx.x, t = threadIdx.x;
    long long off = (long long)row * DIM;
    float inv = 1.f / fmaxf(g_deg[row], 1.f);
    float v0 = g_base[off+t]     + g_agg[off+t]*inv     + g_self[off+t]     + b_self[t];
    float v1 = g_base[off+t+256] + g_agg[off+t+256]*inv + g_self[off+t+256] + b_self[t+256];
    red[t] = make_float2(v0 + v1, v0*v0 + v1*v1);
    __syncthreads();
    for (int s = 128; s > 0; s >>= 1) {
        if (t < s) { red[t].x += red[t+s].x; red[t].y += red[t+s].y; }
        __syncthreads();
    }
    float m = red[0].x * (1.f/DIM);
    float var = red[0].y * (1.f/DIM) - m*m;
    float r = rsqrtf(var + 1e-5f);
    float x0 = (v0 - m)*r*gw[t]     + gb[t];
    float x1 = (v1 - m)*r*gw[t+256] + gb[t+256];
    g_x1[off+t] = x0; g_x1[off+t+256] = x1;
    g_x1h[off+t]     = __float2half(x0);
    g_x1h[off+t+256] = __float2half(x1);
}

// ---------------- final fused: LN2 -> out-LN -> graph mix ---------------------
__global__ void final_fuse_kernel(const float* __restrict__ bf2,
                                  const float* __restrict__ n2g, const float* __restrict__ n2b,
                                  const float* __restrict__ og,  const float* __restrict__ ob,
                                  const float* __restrict__ gml, float* __restrict__ out) {
    __shared__ float2 red[256];
    int row = blockIdx.x, t = threadIdx.x;
    long long off = (long long)row * DIM;
    float t0 = g_x1[off+t]     + g_agg[off+t]     + bf2[t];
    float t1 = g_x1[off+t+256] + g_agg[off+t+256] + bf2[t+256];
    red[t] = make_float2(t0 + t1, t0*t0 + t1*t1);
    __syncthreads();
    for (int s = 128; s > 0; s >>= 1) {
        if (t < s) { red[t].x += red[t+s].x; red[t].y += red[t+s].y; }
        __syncthreads();
    }
    float m = red[0].x * (1.f/DIM);
    float var = red[0].y * (1.f/DIM) - m*m;
    float r = rsqrtf(var + 1e-5f);
    float x20 = (t0 - m)*r*n2g[t]     + n2b[t];
    float x21 = (t1 - m)*r*n2g[t+256] + n2b[t+256];
    __syncthreads();
    red[t] = make_float2(x20 + x21, x20*x20 + x21*x21);
    __syncthreads();
    for (int s = 128; s > 0; s >>= 1) {
        if (t < s) { red[t].x += red[t+s].x; red[t].y += red[t+s].y; }
        __syncthreads();
    }
    m = red[0].x * (1.f/DIM);
    var = red[0].y * (1.f/DIM) - m*m;
    r = rsqrtf(var + 1e-5f);
    float x30 = (x20 - m)*r*og[t]     + ob[t];
    float x31 = (x21 - m)*r*og[t+256] + ob[t+256];
    float gm = 1.f / (1.f + expf(-gml[0]));
    float b0 = g_base[off+t], b1 = g_base[off+t+256];
    out[off+t]     = b0 + gm*(x30 - b0);
    out[off+t+256] = b1 + gm*(x31 - b1);
}

// ---------------- pooling -----------------------------------------------------
__global__ void pool_part_kernel(const float* __restrict__ x) {
    int b = blockIdx.x;
    int t = threadIdx.x;
    float s = 0.f;
    for (int r = b; r < NN; r += 256)
        s += x[(long long)r*DIM + t];
    g_part[b*DIM + t] = s;
}

__global__ void pool_final_kernel(const float* __restrict__ x, const float* __restrict__ dml,
                                  float* __restrict__ pooled) {
    int t = threadIdx.x;
    float s = 0.f;
    for (int b = 0; b < 256; ++b) s += g_part[b*DIM + t];
    float mean = s * (1.f / NN);
    float dm = 1.f / (1.f + expf(-dml[0]));
    pooled[t] = dm * x[t] + (1.f - dm) * mean;
}

// ---------------- host launcher ----------------------------------------------
extern "C" void kernel_launch(void* const* d_in, const int* in_sizes, int n_in,
                              void* d_out, int out_size) {
    (void)in_sizes; (void)n_in; (void)out_size;
    const float* nf     = (const float*)d_in[0];
    const void*  ei     = d_in[1];
    const void*  et     = d_in[2];
    const void*  ntype  = d_in[3];
    const float* ew     = (const float*)d_in[4];
    const float* emb    = (const float*)d_in[5];
    const float* W_self = (const float*)d_in[6];
    const float* b_self = (const float*)d_in[7];
    const float* W_rel  = (const float*)d_in[8];
    const float* b_rel  = (const float*)d_in[9];
    const float* in_g   = (const float*)d_in[10];
    const float* in_b   = (const float*)d_in[11];
    const float* n1_g   = (const float*)d_in[12];
    const float* n1_b   = (const float*)d_in[13];
    const float* Wf1    = (const float*)d_in[14];
    const float* bf1    = (const float*)d_in[15];
    const float* Wf2    = (const float*)d_in[16];
    const float* bf2    = (const float*)d_in[17];
    const float* n2_g   = (const float*)d_in[18];
    const float* n2_b   = (const float*)d_in[19];
    const float* out_g  = (const float*)d_in[20];
    const float* out_b  = (const float*)d_in[21];
    const float* gml    = (const float*)d_in[22];
    const float* dml    = (const float*)d_in[23];
    float* out = (float*)d_out;

    static bool init = false;
    static float *p_agg, *p_self;
    static __half *p_yh, *p_bh, *p_x1h, *p_uh, *p_wh;
    static int *p_rowlist;
    if (!init) {
        cudaGetSymbolAddress((void**)&p_yh,      g_yh);
        cudaGetSymbolAddress((void**)&p_agg,     g_agg);
        cudaGetSymbolAddress((void**)&p_self,    g_self);
        cudaGetSymbolAddress((void**)&p_bh,      g_baseh);
        cudaGetSymbolAddress((void**)&p_x1h,     g_x1h);
        cudaGetSymbolAddress((void**)&p_uh,      g_uh);
        cudaGetSymbolAddress((void**)&p_wh,      g_wh);
        cudaGetSymbolAddress((void**)&p_rowlist, g_rowlist);
        init = true;
    }

    const int MROWS = (NN + GBM - 1) / GBM;   // 391
    const int SMEMB = 32768;

    detect_idx_kernel<<<1, 256>>>((const unsigned int*)ei);
    zero_kernel<<<1024, 256>>>();
    input_ln_kernel<<<NN, 256>>>(nf, ntype, emb, in_g, in_b);
    conv_w_kernel<<<2048, 256>>>(W_rel,  NRELS*DIM*DIM, WREL_OFF);
    conv_w_kernel<<<512,  256>>>(W_self, DIM*DIM,       WSELF_OFF);
    conv_w_kernel<<<1024, 256>>>(Wf1,    FFDIM*DIM,     WF1_OFF);
    conv_w_kernel<<<1024, 256>>>(Wf2,    DIM*FFDIM,     WF2_OFF);

    // compaction of (rel, src) pairs
    mark_kernel<<<(TOTE + 255)/256, 256>>>(ei, et, ew);
    scan_sum_kernel<<<SCAN_NB, 512>>>();
    scan_off_kernel<<<1, 512>>>();
    scan_write_kernel<<<SCAN_NB, 512>>>();

    // y[rel][i] = fp16(base[rowlist[rel][i]] @ W_rel[rel].T + b_rel[rel])
    {
        dim3 grid(DIM / GBN, MROWS, NRELS);
        gemm_f16<<<grid, 128, SMEMB>>>(p_bh, p_wh + WREL_OFF, nullptr, p_yh, b_rel,
                                       p_rowlist,
                                       NN, DIM, DIM, (long long)DIM*DIM,
                                       (long long)NN*DIM, DIM, 1);
    }
    scatter_kernel<<<TOTE, 128>>>(ei, et, ew);
    // self = base @ W_self.T  (fp32)
    {
        dim3 grid(DIM / GBN, MROWS, 1);
        gemm_f16<<<grid, 128, SMEMB>>>(p_bh, p_wh + WSELF_OFF, p_self, nullptr, nullptr,
                                       nullptr, NN, DIM, DIM, 0, 0, 0, 0);
    }
    ln1_kernel<<<NN, 256>>>(b_self, n1_g, n1_b);

    // FFN1 (+bias+gelu fused, fp16 output)
    {
        dim3 grid(FFDIM / GBN, MROWS, 1);
        gemm_f16<<<grid, 128, SMEMB>>>(p_x1h, p_wh + WF1_OFF, nullptr, p_uh, bf1,
                                       nullptr, NN, FFDIM, DIM, 0, 0, 0, 2);
    }
    // FFN2 -> g_agg fp32 (bf2 added in final_fuse)
    {
        dim3 grid(DIM / GBN, MROWS, 1);
        gemm_f16<<<grid, 128, SMEMB>>>(p_uh, p_wh + WF2_OFF, p_agg, nullptr, nullptr,
                                       nullptr, NN, DIM, FFDIM, 0, 0, 0, 0);
    }

    final_fuse_kernel<<<NN, 256>>>(bf2, n2_g, n2_b, out_g, out_b, gml, out);
    pool_part_kernel<<<256, 512>>>(out);
    pool_final_kernel<<<1, 512>>>(out, dml, out + (long long)NN*DIM);
}

// round 10
// speedup vs baseline: 1.0076x; 1.0076x over previous
#include <cuda_runtime.h>
#include <cuda_fp16.h>
#include <math.h>
#include <stdint.h>

#define DIM 512
#define NN 50000
#define NE 100000
#define TOTE (2*NE)
#define NRELS 4
#define FFDIM 1024
#define NNP 50176              // 98*512, padded per-rel stride for scan alignment
#define SCAN_NB 392            // 4*98 blocks of 512

// ---------------- scratch (device globals; no allocation allowed) -------------
__device__ __half g_yh[NRELS*NN*DIM];    // per-rel transformed nodes (fp16, compact rows)
__device__ float g_deg[NN];
__device__ float g_base[NN*DIM];
__device__ __half g_baseh[NN*DIM];
__device__ float g_agg[NN*DIM];          // scatter target / reused as FFN2 out
__device__ float g_self[NN*DIM];
__device__ float g_x1[NN*DIM];
__device__ __half g_x1h[NN*DIM];
__device__ __half g_uh[NN*FFDIM];        // FFN hidden (post-gelu) fp16
#define NWELEM 2359296
#define WREL_OFF 0
#define WSELF_OFF 1048576
#define WF1_OFF 1310720
#define WF2_OFF 1835008
__device__ __half g_wh[NWELEM];
__device__ float g_part[256*DIM];
__device__ int   g_is64;
// compaction state
__device__ int g_mark[NRELS*NNP];        // 200704 = 392*512
__device__ int g_bsum[SCAN_NB];
__device__ int g_boff[SCAN_NB+8];
__device__ int g_cnt[NRELS];
__device__ int g_rowlist[NRELS*NN];      // compact idx -> src node (per rel)
__device__ int g_posmap[NRELS*NNP];      // (rel,src) -> compact idx

// ---------------- index dtype detection --------------------------------------
__global__ void detect_idx_kernel(const unsigned int* __restrict__ w) {
    __shared__ int nz;
    if (threadIdx.x == 0) nz = 0;
    __syncthreads();
    int found = 0;
    for (int i = threadIdx.x; i < TOTE/2 * 2; i += blockDim.x) {
        if (w[2*i + 1] != 0u) { found = 1; break; }
        if (2*i + 1 >= TOTE - 1) break;
    }
    if (found) atomicOr(&nz, 1);
    __syncthreads();
    if (threadIdx.x == 0) g_is64 = nz ? 0 : 1;
}

__device__ __forceinline__ int ldidx(const void* p, long long i) {
    return g_is64 ? (int)((const long long*)p)[i] : ((const int*)p)[i];
}

// ---------------- edge decode --------------------------------------------------
__device__ __forceinline__ void edge_decode(const void* ei, const void* et,
                                            const float* ew, int e,
                                            int& src, int& dst, int& rel, float& w) {
    if (e < NE) {
        src = ldidx(ei, e); dst = ldidx(ei, NE + e);
        rel = ldidx(et, e); w = ew[e];
    } else {
        int e2 = e - NE;
        src = ldidx(ei, NE + e2); dst = ldidx(ei, e2);
        rel = ldidx(et, e2) + 2;  w = ew[e2];
    }
}

// ---------------- zero agg + deg + mark ---------------------------------------
__global__ void zero_kernel() {
    long long n4 = (long long)NN*DIM/4;
    float4* s4 = (float4*)g_agg;
    float4 z = make_float4(0.f,0.f,0.f,0.f);
    long long stride = (long long)gridDim.x * blockDim.x;
    for (long long i = (long long)blockIdx.x*blockDim.x + threadIdx.x; i < n4; i += stride)
        s4[i] = z;
    for (int i = blockIdx.x*blockDim.x + threadIdx.x; i < NN; i += (int)stride)
        g_deg[i] = 0.f;
    for (int i = blockIdx.x*blockDim.x + threadIdx.x; i < NRELS*NNP; i += (int)stride)
        g_mark[i] = 0;
}

// ---------------- compaction: mark / scan / write ------------------------------
__global__ void mark_kernel(const void* __restrict__ ei, const void* __restrict__ et,
                            const float* __restrict__ ew) {
    int e = blockIdx.x * blockDim.x + threadIdx.x;
    if (e >= TOTE) return;
    int src, dst, rel; float w;
    edge_decode(ei, et, ew, e, src, dst, rel, w);
    g_mark[rel*NNP + src] = 1;
}

__global__ void scan_sum_kernel() {          // SCAN_NB blocks x 512
    __shared__ int sh[512];
    int b = blockIdx.x, t = threadIdx.x;
    sh[t] = g_mark[b*512 + t];
    __syncthreads();
    for (int s = 256; s > 0; s >>= 1) {
        if (t < s) sh[t] += sh[t+s];
        __syncthreads();
    }
    if (t == 0) g_bsum[b] = sh[0];
}

__global__ void scan_off_kernel() {          // 1 block x 512
    __shared__ int sh[512];
    int t = threadIdx.x;
    sh[t] = (t < SCAN_NB) ? g_bsum[t] : 0;
    __syncthreads();
    for (int s = 1; s < 512; s <<= 1) {
        int v = (t >= s) ? sh[t-s] : 0;
        __syncthreads();
        sh[t] += v;
        __syncthreads();
    }
    if (t < SCAN_NB) g_boff[t+1] = sh[t];
    if (t == 0) g_boff[0] = 0;
    __syncthreads();
    if (t < NRELS) {
        int lo = (t == 0) ? 0 : sh[98*t - 1];
        int hi = sh[98*(t+1) - 1];
        g_cnt[t] = hi - lo;
    }
}

__global__ void scan_write_kernel() {        // SCAN_NB blocks x 512
    __shared__ int sh[512];
    int b = blockIdx.x, t = threadIdx.x;
    int j = b*512 + t;
    int m = g_mark[j];
    sh[t] = m;
    __syncthreads();
    for (int s = 1; s < 512; s <<= 1) {
        int v = (t >= s) ? sh[t-s] : 0;
        __syncthreads();
        sh[t] += v;
        __syncthreads();
    }
    if (m) {
        int gpos = g_boff[b] + sh[t] - m;   // exclusive global position
        int rel = b / 98;
        int src = j - rel*NNP;
        int li = gpos - g_boff[rel*98];
        g_rowlist[rel*NN + li] = src;
        g_posmap[j] = li;
    }
}

// ---------------- input LayerNorm ---------------------------------------------
__global__ void input_ln_kernel(const float* __restrict__ nf, const void* __restrict__ ntype,
                                const float* __restrict__ emb, const float* __restrict__ gw,
                                const float* __restrict__ gb) {
    __shared__ float2 red[256];
    int row = blockIdx.x, t = threadIdx.x;
    int nt = ldidx(ntype, row);
    long long off = (long long)row * DIM;
    float v0 = nf[off + t]       + emb[nt*DIM + t];
    float v1 = nf[off + t + 256] + emb[nt*DIM + t + 256];
    red[t] = make_float2(v0 + v1, v0*v0 + v1*v1);
    __syncthreads();
    for (int s = 128; s > 0; s >>= 1) {
        if (t < s) { red[t].x += red[t+s].x; red[t].y += red[t+s].y; }
        __syncthreads();
    }
    float m = red[0].x * (1.f/DIM);
    float var = red[0].y * (1.f/DIM) - m*m;
    float r = rsqrtf(var + 1e-5f);
    float b0 = (v0 - m)*r*gw[t]     + gb[t];
    float b1 = (v1 - m)*r*gw[t+256] + gb[t+256];
    g_base[off + t]       = b0;
    g_base[off + t + 256] = b1;
    g_baseh[off + t]       = __float2half(b0);
    g_baseh[off + t + 256] = __float2half(b1);
}

// ---------------- edge scatter: agg[dst] += w * y[rel][pos(src)] ---------------
__global__ void scatter_kernel(const void* __restrict__ ei, const void* __restrict__ et,
                               const float* __restrict__ ew) {
    int e = blockIdx.x;
    int t = threadIdx.x;   // 0..127, 4 halves each
    int src, dst, rel; float w;
    edge_decode(ei, et, ew, e, src, dst, rel, w);
    int li = g_posmap[rel*NNP + src];
    const uint2* yrow = (const uint2*)(g_yh + ((long long)rel*NN + li)*DIM);
    uint2 pk = yrow[t];
    __half2 p0 = *(__half2*)&pk.x;
    __half2 p1 = *(__half2*)&pk.y;
    float4 v;
    v.x = w * __half2float(p0.x);
    v.y = w * __half2float(p0.y);
    v.z = w * __half2float(p1.x);
    v.w = w * __half2float(p1.y);
    float* p = g_agg + (long long)dst*DIM + t*4;
    asm volatile("red.global.add.v4.f32 [%0], {%1,%2,%3,%4};"
                 :: "l"(p), "f"(v.x), "f"(v.y), "f"(v.z), "f"(v.w) : "memory");
    if (t == 0) atomicAdd(&g_deg[dst], w);
}

// ---------------- weight convert ----------------------------------------------
__global__ void conv_w_kernel(const float* __restrict__ src, int n, int off) {
    for (int i = blockIdx.x*blockDim.x + threadIdx.x; i < n; i += gridDim.x*blockDim.x)
        g_wh[off + i] = __float2half(src[i]);
}

// ================= fp16 tensor-core GEMM (NT, mma.sync) =======================
#define GBM 128
#define GBN 128
#define GBK 32

__device__ __forceinline__ void ldsm4(uint32_t* r, uint32_t addr) {
    asm volatile("ldmatrix.sync.aligned.m8n8.x4.shared.b16 {%0,%1,%2,%3},[%4];\n"
        : "=r"(r[0]), "=r"(r[1]), "=r"(r[2]), "=r"(r[3]) : "r"(addr));
}
__device__ __forceinline__ void mma_f16(float* d, const uint32_t* a, uint32_t b0, uint32_t b1) {
    asm volatile("mma.sync.aligned.m16n8k16.row.col.f32.f16.f16.f32 "
        "{%0,%1,%2,%3},{%4,%5,%6,%7},{%8,%9},{%0,%1,%2,%3};\n"
        : "+f"(d[0]), "+f"(d[1]), "+f"(d[2]), "+f"(d[3])
        : "r"(a[0]), "r"(a[1]), "r"(a[2]), "r"(a[3]), "r"(b0), "r"(b1));
}
__device__ __forceinline__ void cp16(uint32_t dst, const void* src, int sz) {
    asm volatile("cp.async.cg.shared.global [%0],[%1],16,%2;\n" :: "r"(dst), "l"(src), "r"(sz));
}

// mode: 0 = fp32 C = acc (+bias if bias)   1 = fp16 O = acc + bias
//       2 = fp16 O = gelu(acc + bias)
// rowlist != null: A rows gathered via rowlist[z*NN + r], M_eff = g_cnt[z]
// A-row indices + valid flags are hoisted into registers ONCE per CTA (they are
// k-loop-invariant); issue_copy is pure cp.async with no dependent global loads.
__global__ void __launch_bounds__(128) gemm_f16(
    const __half* __restrict__ A, const __half* __restrict__ B,
    float* __restrict__ C, __half* __restrict__ O, const float* __restrict__ bias,
    const int* __restrict__ rowlist,
    int M, int N, int K, long long bStrideZ, long long outStrideZ, long long biasStrideZ, int mode)
{
    extern __shared__ __align__(1024) char smraw[];
    const int tid = threadIdx.x;
    const int lane = tid & 31, wid = tid >> 5;
    const int wm = wid >> 1, wn = wid & 1;
    const int bm = blockIdx.y * GBM, bn = blockIdx.x * GBN, z = blockIdx.z;
    int Meff = M;
    const int* rlz = nullptr;
    if (rowlist) {
        Meff = g_cnt[z];
        if (bm >= Meff) return;
        rlz = rowlist + (long long)z * NN;
    }
    const __half* Bz = B + (long long)z * bStrideZ;
    const int niter = K / GBK;
    uint32_t smbase = (uint32_t)__cvta_generic_to_shared(smraw);

    // ---- hoisted A-row gather indices (k-invariant) --------------------------
    const int cc = tid & 3;        // 16B chunk within a 64B k-slice
    const int rr = tid >> 2;       // row-within-32-group
    long long arow[4];
    int avalid[4];
    #pragma unroll
    for (int i = 0; i < 4; i++) {
        int gr = bm + i*32 + rr;
        bool ok = (gr < Meff);
        int node = ok ? (rlz ? rlz[gr] : gr) : 0;
        arow[i] = (long long)node * K;
        avalid[i] = ok ? 16 : 0;
    }

    float acc[4][8][4];
    #pragma unroll
    for (int i = 0; i < 4; i++)
        #pragma unroll
        for (int j = 0; j < 8; j++)
            #pragma unroll
            for (int c = 0; c < 4; c++) acc[i][j][c] = 0.f;

    auto issue_copy = [&](int stage, int it) {
        int kb = it * GBK;
        #pragma unroll
        for (int i = 0; i < 4; i++) {
            int row = i*32 + rr;
            uint32_t dst = smbase + stage*16384
                         + (uint32_t)(row*64 + ((cc ^ ((row>>1)&3)) << 4));
            cp16(dst, A + arow[i] + kb + cc*8, avalid[i]);
        }
        #pragma unroll
        for (int i = 0; i < 4; i++) {
            int row = i*32 + rr;
            uint32_t dst = smbase + stage*16384 + 8192
                         + (uint32_t)(row*64 + ((cc ^ ((row>>1)&3)) << 4));
            cp16(dst, Bz + (long long)(bn + row)*K + kb + cc*8, 16);
        }
        asm volatile("cp.async.commit_group;\n" ::: "memory");
    };

    issue_copy(0, 0);

    for (int it = 0; it < niter; ++it) {
        if (it + 1 < niter) {
            issue_copy((it + 1) & 1, it + 1);
            asm volatile("cp.async.wait_group 1;\n" ::: "memory");
        } else {
            asm volatile("cp.async.wait_group 0;\n" ::: "memory");
        }
        __syncthreads();

        uint32_t sA = smbase + (it & 1)*16384;
        uint32_t sB = sA + 8192;
        int rsel = lane & 15;
        #pragma unroll
        for (int kk = 0; kk < 2; kk++) {
            int csel = kk*2 + (lane >> 4);
            uint32_t ah[4][4], bh[4][4];
            #pragma unroll
            for (int mi = 0; mi < 4; mi++) {
                int row = wm*64 + mi*16 + rsel;
                uint32_t off = (uint32_t)(row*64 + ((csel ^ ((row>>1)&3)) << 4));
                ldsm4(ah[mi], sA + off);
            }
            #pragma unroll
            for (int p = 0; p < 4; p++) {
                int row = wn*64 + p*16 + rsel;
                uint32_t off = (uint32_t)(row*64 + ((csel ^ ((row>>1)&3)) << 4));
                ldsm4(bh[p], sB + off);
            }
            #pragma unroll
            for (int mi = 0; mi < 4; mi++)
                #pragma unroll
                for (int nj = 0; nj < 8; nj++) {
                    int p = nj >> 1, h = nj & 1;
                    mma_f16(acc[mi][nj], ah[mi], bh[p][h], bh[p][2+h]);
                }
        }
        __syncthreads();
    }

    // ---- epilogue -----------------------------------------------------------
    #pragma unroll
    for (int mi = 0; mi < 4; mi++) {
        #pragma unroll
        for (int nj = 0; nj < 8; nj++) {
            int gc = bn + wn*64 + nj*8 + (lane & 3)*2;
            #pragma unroll
            for (int half = 0; half < 2; half++) {
                int gr = bm + wm*64 + mi*16 + (lane >> 2) + half*8;
                if (gr >= Meff) continue;
                float v0 = acc[mi][nj][half*2 + 0];
                float v1 = acc[mi][nj][half*2 + 1];
                if (mode == 0) {
                    if (bias) {
                        const float* bs = bias + (long long)z*biasStrideZ;
                        v0 += bs[gc]; v1 += bs[gc+1];
                    }
                    float* Cp = C + (long long)z*outStrideZ + (long long)gr*N + gc;
                    float2 w2 = make_float2(v0, v1);
                    *(float2*)Cp = w2;
                } else {
                    const float* bs = bias + (long long)z*biasStrideZ;
                    v0 += bs[gc]; v1 += bs[gc+1];
                    if (mode == 2) {
                        v0 = 0.5f * v0 * (1.f + erff(v0 * 0.70710678118654752f));
                        v1 = 0.5f * v1 * (1.f + erff(v1 * 0.70710678118654752f));
                    }
                    __half2 o;
                    o.x = __float2half(v0);
                    o.y = __float2half(v1);
                    *(__half2*)(O + (long long)z*outStrideZ + (long long)gr*N + gc) = o;
                }
            }
        }
    }
}

// ---------------- LN1: x1 = LN(base + agg/max(deg,1) + self + b_self) ---------
__global__ void ln1_kernel(const float* __restrict__ b_self, const float* __restrict__ gw,
                           const float* __restrict__ gb) {
    __shared__ float2 red[256];
    int row = blockIdx.x, t = threadIdx.x;
    long long off = (long long)row * DIM;
    float inv = 1.f / fmaxf(g_deg[row], 1.f);
    float v0 = g_base[off+t]     + g_agg[off+t]*inv     + g_self[off+t]     + b_self[t];
    float v1 = g_base[off+t+256] + g_agg[off+t+256]*inv + g_self[off+t+256] + b_self[t+256];
    red[t] = make_float2(v0 + v1, v0*v0 + v1*v1);
    __syncthreads();
    for (int s = 128; s > 0; s >>= 1) {
        if (t < s) { red[t].x += red[t+s].x; red[t].y += red[t+s].y; }
        __syncthreads();
    }
    float m = red[0].x * (1.f/DIM);
    float var = red[0].y * (1.f/DIM) - m*m;
    float r = rsqrtf(var + 1e-5f);
    float x0 = (v0 - m)*r*gw[t]     + gb[t];
    float x1 = (v1 - m)*r*gw[t+256] + gb[t+256];
    g_x1[off+t] = x0; g_x1[off+t+256] = x1;
    g_x1h[off+t]     = __float2half(x0);
    g_x1h[off+t+256] = __float2half(x1);
}

// ---------------- final fused: LN2 -> out-LN -> graph mix ---------------------
__global__ void final_fuse_kernel(const float* __restrict__ bf2,
                                  const float* __restrict__ n2g, const float* __restrict__ n2b,
                                  const float* __restrict__ og,  const float* __restrict__ ob,
                                  const float* __restrict__ gml, float* __restrict__ out) {
    __shared__ float2 red[256];
    int row = blockIdx.x, t = threadIdx.x;
    long long off = (long long)row * DIM;
    float t0 = g_x1[off+t]     + g_agg[off+t]     + bf2[t];
    float t1 = g_x1[off+t+256] + g_agg[off+t+256] + bf2[t+256];
    red[t] = make_float2(t0 + t1, t0*t0 + t1*t1);
    __syncthreads();
    for (int s = 128; s > 0; s >>= 1) {
        if (t < s) { red[t].x += red[t+s].x; red[t].y += red[t+s].y; }
        __syncthreads();
    }
    float m = red[0].x * (1.f/DIM);
    float var = red[0].y * (1.f/DIM) - m*m;
    float r = rsqrtf(var + 1e-5f);
    float x20 = (t0 - m)*r*n2g[t]     + n2b[t];
    float x21 = (t1 - m)*r*n2g[t+256] + n2b[t+256];
    __syncthreads();
    red[t] = make_float2(x20 + x21, x20*x20 + x21*x21);
    __syncthreads();
    for (int s = 128; s > 0; s >>= 1) {
        if (t < s) { red[t].x += red[t+s].x; red[t].y += red[t+s].y; }
        __syncthreads();
    }
    m = red[0].x * (1.f/DIM);
    var = red[0].y * (1.f/DIM) - m*m;
    r = rsqrtf(var + 1e-5f);
    float x30 = (x20 - m)*r*og[t]     + ob[t];
    float x31 = (x21 - m)*r*og[t+256] + ob[t+256];
    float gm = 1.f / (1.f + expf(-gml[0]));
    float b0 = g_base[off+t], b1 = g_base[off+t+256];
    out[off+t]     = b0 + gm*(x30 - b0);
    out[off+t+256] = b1 + gm*(x31 - b1);
}

// ---------------- pooling -----------------------------------------------------
__global__ void pool_part_kernel(const float* __restrict__ x) {
    int b = blockIdx.x;
    int t = threadIdx.x;
    float s = 0.f;
    for (int r = b; r < NN; r += 256)
        s += x[(long long)r*DIM + t];
    g_part[b*DIM + t] = s;
}

__global__ void pool_final_kernel(const float* __restrict__ x, const float* __restrict__ dml,
                                  float* __restrict__ pooled) {
    int t = threadIdx.x;
    float s = 0.f;
    for (int b = 0; b < 256; ++b) s += g_part[b*DIM + t];
    float mean = s * (1.f / NN);
    float dm = 1.f / (1.f + expf(-dml[0]));
    pooled[t] = dm * x[t] + (1.f - dm) * mean;
}

// ---------------- host launcher ----------------------------------------------
extern "C" void kernel_launch(void* const* d_in, const int* in_sizes, int n_in,
                              void* d_out, int out_size) {
    (void)in_sizes; (void)n_in; (void)out_size;
    const float* nf     = (const float*)d_in[0];
    const void*  ei     = d_in[1];
    const void*  et     = d_in[2];
    const void*  ntype  = d_in[3];
    const float* ew     = (const float*)d_in[4];
    const float* emb    = (const float*)d_in[5];
    const float* W_self = (const float*)d_in[6];
    const float* b_self = (const float*)d_in[7];
    const float* W_rel  = (const float*)d_in[8];
    const float* b_rel  = (const float*)d_in[9];
    const float* in_g   = (const float*)d_in[10];
    const float* in_b   = (const float*)d_in[11];
    const float* n1_g   = (const float*)d_in[12];
    const float* n1_b   = (const float*)d_in[13];
    const float* Wf1    = (const float*)d_in[14];
    const float* bf1    = (const float*)d_in[15];
    const float* Wf2    = (const float*)d_in[16];
    const float* bf2    = (const float*)d_in[17];
    const float* n2_g   = (const float*)d_in[18];
    const float* n2_b   = (const float*)d_in[19];
    const float* out_g  = (const float*)d_in[20];
    const float* out_b  = (const float*)d_in[21];
    const float* gml    = (const float*)d_in[22];
    const float* dml    = (const float*)d_in[23];
    float* out = (float*)d_out;

    static bool init = false;
    static float *p_agg, *p_self;
    static __half *p_yh, *p_bh, *p_x1h, *p_uh, *p_wh;
    static int *p_rowlist;
    if (!init) {
        cudaGetSymbolAddress((void**)&p_yh,      g_yh);
        cudaGetSymbolAddress((void**)&p_agg,     g_agg);
        cudaGetSymbolAddress((void**)&p_self,    g_self);
        cudaGetSymbolAddress((void**)&p_bh,      g_baseh);
        cudaGetSymbolAddress((void**)&p_x1h,     g_x1h);
        cudaGetSymbolAddress((void**)&p_uh,      g_uh);
        cudaGetSymbolAddress((void**)&p_wh,      g_wh);
        cudaGetSymbolAddress((void**)&p_rowlist, g_rowlist);
        init = true;
    }

    const int MROWS = (NN + GBM - 1) / GBM;   // 391
    const int SMEMB = 32768;

    detect_idx_kernel<<<1, 256>>>((const unsigned int*)ei);
    zero_kernel<<<1024, 256>>>();
    input_ln_kernel<<<NN, 256>>>(nf, ntype, emb, in_g, in_b);
    conv_w_kernel<<<2048, 256>>>(W_rel,  NRELS*DIM*DIM, WREL_OFF);
    conv_w_kernel<<<512,  256>>>(W_self, DIM*DIM,       WSELF_OFF);
    conv_w_kernel<<<1024, 256>>>(Wf1,    FFDIM*DIM,     WF1_OFF);
    conv_w_kernel<<<1024, 256>>>(Wf2,    DIM*FFDIM,     WF2_OFF);

    // compaction of (rel, src) pairs
    mark_kernel<<<(TOTE + 255)/256, 256>>>(ei, et, ew);
    scan_sum_kernel<<<SCAN_NB, 512>>>();
    scan_off_kernel<<<1, 512>>>();
    scan_write_kernel<<<SCAN_NB, 512>>>();

    // y[rel][i] = fp16(base[rowlist[rel][i]] @ W_rel[rel].T + b_rel[rel])
    {
        dim3 grid(DIM / GBN, MROWS, NRELS);
        gemm_f16<<<grid, 128, SMEMB>>>(p_bh, p_wh + WREL_OFF, nullptr, p_yh, b_rel,
                                       p_rowlist,
                                       NN, DIM, DIM, (long long)DIM*DIM,
                                       (long long)NN*DIM, DIM, 1);
    }
    scatter_kernel<<<TOTE, 128>>>(ei, et, ew);
    // self = base @ W_self.T  (fp32)
    {
        dim3 grid(DIM / GBN, MROWS, 1);
        gemm_f16<<<grid, 128, SMEMB>>>(p_bh, p_wh + WSELF_OFF, p_self, nullptr, nullptr,
                                       nullptr, NN, DIM, DIM, 0, 0, 0, 0);
    }
    ln1_kernel<<<NN, 256>>>(b_self, n1_g, n1_b);

    // FFN1 (+bias+gelu fused, fp16 output)
    {
        dim3 grid(FFDIM / GBN, MROWS, 1);
        gemm_f16<<<grid, 128, SMEMB>>>(p_x1h, p_wh + WF1_OFF, nullptr, p_uh, bf1,
                                       nullptr, NN, FFDIM, DIM, 0, 0, 0, 2);
    }
    // FFN2 -> g_agg fp32 (bf2 added in final_fuse)
    {
        dim3 grid(DIM / GBN, MROWS, 1);
        gemm_f16<<<grid, 128, SMEMB>>>(p_uh, p_wh + WF2_OFF, p_agg, nullptr, nullptr,
                                       nullptr, NN, DIM, FFDIM, 0, 0, 0, 0);
    }

    final_fuse_kernel<<<NN, 256>>>(bf2, n2_g, n2_b, out_g, out_b, gml, out);
    pool_part_kernel<<<256, 512>>>(out);
    pool_final_kernel<<<1, 512>>>(out, dml, out + (long long)NN*DIM);
}